// round 3
// baseline (speedup 1.0000x reference)
#include <cuda_runtime.h>
#include <cstdint>

// ---------------- problem constants ----------------
#define BATCH      4
#define N1_PER     16384
#define N2_PER     4096
#define N1_TOT     (BATCH * N1_PER)    // 65536
#define N2_TOT     (BATCH * N2_PER)    // 16384
#define C_IN       512
#define C_OUT      256
#define BN_EPS     1e-5f

// ---------------- device scratch (static, allocation-free) ----------------
__device__ float g_h2[N2_TOT * C_OUT];       // 16 MB: relu(bn(x2@W2^T))
__device__ float g_W1f[C_OUT * C_OUT];       // BN-folded weights
__device__ float g_W2f[C_OUT * C_IN];
__device__ float g_c1[C_OUT];                // BN-folded bias
__device__ float g_c2[C_OUT];

// ---------------- f32x2 helpers (Blackwell packed fp32 FMA) ----------------
struct __align__(16) ull2 { unsigned long long x, y; };

__device__ __forceinline__ unsigned long long pack2(float lo, float hi) {
    unsigned long long r;
    asm("mov.b64 %0, {%1, %2};" : "=l"(r) : "r"(__float_as_uint(lo)), "r"(__float_as_uint(hi)));
    return r;
}
__device__ __forceinline__ void unpack2(unsigned long long v, float& lo, float& hi) {
    unsigned int a, b;
    asm("mov.b64 {%0, %1}, %2;" : "=r"(a), "=r"(b) : "l"(v));
    lo = __uint_as_float(a); hi = __uint_as_float(b);
}
__device__ __forceinline__ void ffma2(unsigned long long& d, unsigned long long a,
                                      unsigned long long b) {
    asm("fma.rn.f32x2 %0, %1, %2, %3;" : "=l"(d) : "l"(a), "l"(b), "l"(d));
}

// ---------------- BN fold: Wf[n,k] = W[n,k]*s_n ; c[n] = (b-m)*s + beta ----
template <int WHICH>
__global__ void fold_kernel(const float* __restrict__ W, const float* __restrict__ b,
                            const float* __restrict__ g, const float* __restrict__ be,
                            const float* __restrict__ m, const float* __restrict__ v)
{
    const int Kd = (WHICH == 0) ? C_OUT : C_IN;
    float* Wf = (WHICH == 0) ? g_W1f : g_W2f;
    float* cf = (WHICH == 0) ? g_c1 : g_c2;
    int n = blockIdx.x;
    float s = g[n] / sqrtf(v[n] + BN_EPS);
    if (threadIdx.x == 0) cf[n] = (b[n] - m[n]) * s + be[n];
    for (int k = threadIdx.x; k < Kd; k += blockDim.x)
        Wf[n * Kd + k] = W[n * Kd + k] * s;
}

// ---------------- fused GEMM + bias + ReLU (f32x2 inner product) ----------
// C[m,n] = relu( sum_k A[m,k]*Wf[n,k] + c[n] ),  N fixed = 256
// 128x128 tile, BK=8, 256 threads, 8x8 microtile held as 8x4 f32x2 pairs.
template <int WHICH>
__global__ __launch_bounds__(256, 2) void gemm_bias_relu(
    const float* __restrict__ A, float* __restrict__ C, int M, int K)
{
    const float* __restrict__ Bw  = (WHICH == 0) ? g_W1f : g_W2f;
    const float* __restrict__ cb  = (WHICH == 0) ? g_c1  : g_c2;

    __shared__ float As[8][128];
    __shared__ float Bs[8][128];

    const int tid = threadIdx.x;
    const int tx  = tid & 15;        // 0..15 -> n microtile
    const int ty  = tid >> 4;        // 0..15 -> m microtile
    const int bn  = blockIdx.x * 128;
    const int bm  = blockIdx.y * 128;

    const int lr = tid >> 1;         // 0..127 row within tile
    const int lc = (tid & 1) * 4;    // 0 or 4 (k offset)

    const float* Ap = A  + (size_t)(bm + lr) * K + lc;
    const float* Bp = Bw + (size_t)(bn + lr) * K + lc;

    unsigned long long acc[8][4];
#pragma unroll
    for (int i = 0; i < 8; i++)
#pragma unroll
        for (int j = 0; j < 4; j++) acc[i][j] = 0ull;   // bits of (0.f, 0.f)

    for (int k0 = 0; k0 < K; k0 += 8) {
        float4 a = *(const float4*)(Ap + k0);
        float4 b = *(const float4*)(Bp + k0);
        As[lc + 0][lr] = a.x; As[lc + 1][lr] = a.y;
        As[lc + 2][lr] = a.z; As[lc + 3][lr] = a.w;
        Bs[lc + 0][lr] = b.x; Bs[lc + 1][lr] = b.y;
        Bs[lc + 2][lr] = b.z; Bs[lc + 3][lr] = b.w;
        __syncthreads();

#pragma unroll
        for (int kk = 0; kk < 8; kk++) {
            const float4* arow = (const float4*)&As[kk][ty * 8];
            float4 a0 = arow[0], a1 = arow[1];
            unsigned long long aa[8];
            aa[0] = pack2(a0.x, a0.x); aa[1] = pack2(a0.y, a0.y);
            aa[2] = pack2(a0.z, a0.z); aa[3] = pack2(a0.w, a0.w);
            aa[4] = pack2(a1.x, a1.x); aa[5] = pack2(a1.y, a1.y);
            aa[6] = pack2(a1.z, a1.z); aa[7] = pack2(a1.w, a1.w);
            const ull2* brow = (const ull2*)&Bs[kk][tx * 8];
            ull2 b01 = brow[0], b23 = brow[1];
            unsigned long long bb[4] = { b01.x, b01.y, b23.x, b23.y };
#pragma unroll
            for (int i = 0; i < 8; i++)
#pragma unroll
                for (int j = 0; j < 4; j++)
                    ffma2(acc[i][j], aa[i], bb[j]);
        }
        __syncthreads();
    }

    float4 bv0 = *(const float4*)(cb + bn + tx * 8);
    float4 bv1 = *(const float4*)(cb + bn + tx * 8 + 4);
    float bias[8] = { bv0.x, bv0.y, bv0.z, bv0.w, bv1.x, bv1.y, bv1.z, bv1.w };
#pragma unroll
    for (int i = 0; i < 8; i++) {
        size_t m = (size_t)(bm + ty * 8 + i);
        float o[8];
#pragma unroll
        for (int j = 0; j < 4; j++) {
            float lo, hi;
            unpack2(acc[i][j], lo, hi);
            o[2 * j]     = fmaxf(lo + bias[2 * j],     0.f);
            o[2 * j + 1] = fmaxf(hi + bias[2 * j + 1], 0.f);
        }
        *(float4*)(C + m * 256 + bn + tx * 8)     = make_float4(o[0], o[1], o[2], o[3]);
        *(float4*)(C + m * 256 + bn + tx * 8 + 4) = make_float4(o[4], o[5], o[6], o[7]);
    }
}

// ---------------- kNN(k=3) + inverse-distance interp + add into out -------
// Score trick: argmin |q-p|^2 == argmin (|p|^2 - 2 q.p). pts[].w = |p|^2.
// 2 queries per thread (LDS.128 amortized). grid: (N1_PER/512, BATCH).
#define TOP3_UPD(s, kk, A0, A1, A2, I0, I1, I2)            \
    if (s < A2) {                                          \
        if (s < A1) {                                      \
            A2 = A1; I2 = I1;                              \
            if (s < A0) { A1 = A0; I1 = I0; A0 = s; I0 = kk; } \
            else        { A1 = s;  I1 = kk; }              \
        } else { A2 = s; I2 = kk; }                        \
    }

__global__ __launch_bounds__(256) void knn_interp_kernel(
    const float* __restrict__ p1, const float* __restrict__ p2,
    float* __restrict__ out)
{
    extern __shared__ float4 pts[];   // [4096]: (x, y, z, |p|^2)

    const int scene = blockIdx.y;
    const int tid   = threadIdx.x;

    const float* p2s = p2 + (size_t)scene * N2_PER * 3;
    for (int i = tid; i < N2_PER; i += 256) {
        float px = p2s[3 * i + 0], py = p2s[3 * i + 1], pz = p2s[3 * i + 2];
        pts[i] = make_float4(px, py, pz, fmaf(px, px, fmaf(py, py, pz * pz)));
    }
    __syncthreads();

    const int qA = scene * N1_PER + blockIdx.x * 512 + tid;       // query A
    const int qB = qA + 256;                                       // query B
    const float qAx = p1[3 * qA + 0], qAy = p1[3 * qA + 1], qAz = p1[3 * qA + 2];
    const float qBx = p1[3 * qB + 0], qBy = p1[3 * qB + 1], qBz = p1[3 * qB + 2];
    const float nAx = -2.f * qAx, nAy = -2.f * qAy, nAz = -2.f * qAz;
    const float nBx = -2.f * qBx, nBy = -2.f * qBy, nBz = -2.f * qBz;

    float a0 = 3.4e38f, a1 = 3.4e38f, a2 = 3.4e38f;
    float c0 = 3.4e38f, c1 = 3.4e38f, c2 = 3.4e38f;
    int   ia0 = 0, ia1 = 0, ia2 = 0;
    int   ib0 = 0, ib1 = 0, ib2 = 0;

#pragma unroll 4
    for (int k = 0; k < N2_PER; k++) {
        float4 p = pts[k];
        float sA = fmaf(p.x, nAx, fmaf(p.y, nAy, fmaf(p.z, nAz, p.w)));
        float sB = fmaf(p.x, nBx, fmaf(p.y, nBy, fmaf(p.z, nBz, p.w)));
        TOP3_UPD(sA, k, a0, a1, a2, ia0, ia1, ia2);
        TOP3_UPD(sB, k, c0, c1, c2, ib0, ib1, ib2);
    }

    // exact squared distances for the 3 winners, then reference weight formula
    float wA0, wA1, wA2, wB0, wB1, wB2;
    {
        float4 P;
        float dx, dy, dz, d;
        P = pts[ia0]; dx = qAx - P.x; dy = qAy - P.y; dz = qAz - P.z;
        d = fmaf(dx, dx, fmaf(dy, dy, dz * dz));
        wA0 = 1.f / (sqrtf(fmaxf(d, 1e-12f)) + 1e-8f);
        P = pts[ia1]; dx = qAx - P.x; dy = qAy - P.y; dz = qAz - P.z;
        d = fmaf(dx, dx, fmaf(dy, dy, dz * dz));
        wA1 = 1.f / (sqrtf(fmaxf(d, 1e-12f)) + 1e-8f);
        P = pts[ia2]; dx = qAx - P.x; dy = qAy - P.y; dz = qAz - P.z;
        d = fmaf(dx, dx, fmaf(dy, dy, dz * dz));
        wA2 = 1.f / (sqrtf(fmaxf(d, 1e-12f)) + 1e-8f);
        float ws = wA0 + wA1 + wA2;
        wA0 /= ws; wA1 /= ws; wA2 /= ws;

        P = pts[ib0]; dx = qBx - P.x; dy = qBy - P.y; dz = qBz - P.z;
        d = fmaf(dx, dx, fmaf(dy, dy, dz * dz));
        wB0 = 1.f / (sqrtf(fmaxf(d, 1e-12f)) + 1e-8f);
        P = pts[ib1]; dx = qBx - P.x; dy = qBy - P.y; dz = qBz - P.z;
        d = fmaf(dx, dx, fmaf(dy, dy, dz * dz));
        wB1 = 1.f / (sqrtf(fmaxf(d, 1e-12f)) + 1e-8f);
        P = pts[ib2]; dx = qBx - P.x; dy = qBy - P.y; dz = qBz - P.z;
        d = fmaf(dx, dx, fmaf(dy, dy, dz * dz));
        wB2 = 1.f / (sqrtf(fmaxf(d, 1e-12f)) + 1e-8f);
        float ws2 = wB0 + wB1 + wB2;
        wB0 /= ws2; wB1 /= ws2; wB2 /= ws2;
    }

    // warp-cooperative gather: broadcast each lane's (idx, w) triple via shfl,
    // whole warp streams the 256-float rows with coalesced float4 accesses.
    const unsigned full = 0xffffffffu;
    const int warp = tid >> 5, lane = tid & 31;
    const int h2base = scene * N2_PER;

#pragma unroll
    for (int half = 0; half < 2; half++) {
        float w0 = half ? wB0 : wA0, w1 = half ? wB1 : wA1, w2 = half ? wB2 : wA2;
        int   j0 = half ? ib0 : ia0, j1 = half ? ib1 : ia1, j2 = half ? ib2 : ia2;
        const int qbase = scene * N1_PER + blockIdx.x * 512 + half * 256 + warp * 32;

        for (int s = 0; s < 32; s++) {
            float ww0 = __shfl_sync(full, w0, s);
            float ww1 = __shfl_sync(full, w1, s);
            float ww2 = __shfl_sync(full, w2, s);
            int   t0  = __shfl_sync(full, j0, s);
            int   t1  = __shfl_sync(full, j1, s);
            int   t2  = __shfl_sync(full, j2, s);
            const float4* r0 = (const float4*)(g_h2 + (size_t)(h2base + t0) * 256);
            const float4* r1 = (const float4*)(g_h2 + (size_t)(h2base + t1) * 256);
            const float4* r2 = (const float4*)(g_h2 + (size_t)(h2base + t2) * 256);
            float4* o = (float4*)(out + (size_t)(qbase + s) * 256);
#pragma unroll
            for (int c = 0; c < 2; c++) {
                int ci = lane + c * 32;         // 64 float4 slots (256 floats)
                float4 x = r0[ci], y = r1[ci], z = r2[ci], ov = o[ci];
                ov.x += ww0 * x.x + ww1 * y.x + ww2 * z.x;
                ov.y += ww0 * x.y + ww1 * y.y + ww2 * z.y;
                ov.z += ww0 * x.z + ww1 * y.z + ww2 * z.z;
                ov.w += ww0 * x.w + ww1 * y.w + ww2 * z.w;
                o[ci] = ov;
            }
        }
    }
}

// ---------------- launch -----------------
extern "C" void kernel_launch(void* const* d_in, const int* in_sizes, int n_in,
                              void* d_out, int out_size)
{
    const float* p1  = (const float*)d_in[0];
    const float* x1  = (const float*)d_in[1];
    const float* p2  = (const float*)d_in[2];
    const float* x2  = (const float*)d_in[3];
    const float* W1  = (const float*)d_in[4];
    const float* b1  = (const float*)d_in[5];
    const float* g1  = (const float*)d_in[6];
    const float* be1 = (const float*)d_in[7];
    const float* m1  = (const float*)d_in[8];
    const float* v1  = (const float*)d_in[9];
    const float* W2  = (const float*)d_in[10];
    const float* b2  = (const float*)d_in[11];
    const float* g2  = (const float*)d_in[12];
    const float* be2 = (const float*)d_in[13];
    const float* m2  = (const float*)d_in[14];
    const float* v2  = (const float*)d_in[15];
    float* out = (float*)d_out;

    // fold BN into weights/bias
    fold_kernel<0><<<C_OUT, 128>>>(W1, b1, g1, be1, m1, v1);
    fold_kernel<1><<<C_OUT, 128>>>(W2, b2, g2, be2, m2, v2);

    // h1 = relu(bn(x1@W1^T)) -> out directly
    {
        dim3 grid1(2, N1_TOT / 128);
        gemm_bias_relu<0><<<grid1, 256>>>(x1, out, N1_TOT, C_OUT);
    }
    // h2 = relu(bn(x2@W2^T)) -> g_h2
    {
        float* h2ptr = nullptr;
        cudaGetSymbolAddress((void**)&h2ptr, g_h2);
        dim3 grid2(2, N2_TOT / 128);
        gemm_bias_relu<1><<<grid2, 256>>>(x2, h2ptr, N2_TOT, C_IN);
    }

    // kNN interpolation, accumulate into out
    static bool attr_set = false;
    if (!attr_set) {
        cudaFuncSetAttribute(knn_interp_kernel,
                             cudaFuncAttributeMaxDynamicSharedMemorySize,
                             N2_PER * sizeof(float4));
        attr_set = true;
    }
    dim3 gridk(N1_PER / 512, BATCH);
    knn_interp_kernel<<<gridk, 256, N2_PER * sizeof(float4)>>>(p1, p2, out);
}

// round 4
// speedup vs baseline: 1.3590x; 1.3590x over previous
#include <cuda_runtime.h>
#include <cuda_bf16.h>
#include <mma.h>
#include <cstdint>

using namespace nvcuda;

// ---------------- problem constants ----------------
#define BATCH      4
#define N1_PER     16384
#define N2_PER     4096
#define N1_TOT     (BATCH * N1_PER)    // 65536
#define N2_TOT     (BATCH * N2_PER)    // 16384
#define C_IN       512
#define C_OUT      256
#define BN_EPS     1e-5f

// ---------------- device scratch (static, allocation-free) ----------------
__device__ float g_h2[N2_TOT * C_OUT];                    // 16 MB
__device__ __nv_bfloat16 g_x1h[N1_TOT * C_OUT];           // 32 MB
__device__ __nv_bfloat16 g_x1l[N1_TOT * C_OUT];           // 32 MB
__device__ __nv_bfloat16 g_x2h[N2_TOT * C_IN];            // 16 MB
__device__ __nv_bfloat16 g_x2l[N2_TOT * C_IN];            // 16 MB
__device__ __nv_bfloat16 g_W1h[C_OUT * C_OUT];
__device__ __nv_bfloat16 g_W1l[C_OUT * C_OUT];
__device__ __nv_bfloat16 g_W2h[C_OUT * C_IN];
__device__ __nv_bfloat16 g_W2l[C_OUT * C_IN];
__device__ float g_c1[C_OUT];
__device__ float g_c2[C_OUT];

// -------- BN fold + bf16 split of weights: w = W[n,k]*s_n -> (hi, lo) ------
template <int WHICH>
__global__ void fold_convert_W(const float* __restrict__ W, const float* __restrict__ b,
                               const float* __restrict__ g, const float* __restrict__ be,
                               const float* __restrict__ m, const float* __restrict__ v)
{
    const int Kd = (WHICH == 0) ? C_OUT : C_IN;
    __nv_bfloat16* Wh = (WHICH == 0) ? g_W1h : g_W2h;
    __nv_bfloat16* Wl = (WHICH == 0) ? g_W1l : g_W2l;
    float* cf = (WHICH == 0) ? g_c1 : g_c2;
    int n = blockIdx.x;
    float s = g[n] / sqrtf(v[n] + BN_EPS);
    if (threadIdx.x == 0) cf[n] = (b[n] - m[n]) * s + be[n];
    for (int k = threadIdx.x; k < Kd; k += blockDim.x) {
        float w = W[n * Kd + k] * s;
        __nv_bfloat16 h = __float2bfloat16(w);
        Wh[n * Kd + k] = h;
        Wl[n * Kd + k] = __float2bfloat16(w - __bfloat162float(h));
    }
}

// -------- bf16 split of activations ---------------------------------------
__global__ void convert_x(const float* __restrict__ x,
                          __nv_bfloat16* __restrict__ xh,
                          __nv_bfloat16* __restrict__ xl, int n)
{
    int i = (blockIdx.x * blockDim.x + threadIdx.x) * 4;
    if (i >= n) return;
    float4 v = *(const float4*)(x + i);
    __nv_bfloat16 h0 = __float2bfloat16(v.x), h1 = __float2bfloat16(v.y);
    __nv_bfloat16 h2 = __float2bfloat16(v.z), h3 = __float2bfloat16(v.w);
    __nv_bfloat16 l0 = __float2bfloat16(v.x - __bfloat162float(h0));
    __nv_bfloat16 l1 = __float2bfloat16(v.y - __bfloat162float(h1));
    __nv_bfloat16 l2 = __float2bfloat16(v.z - __bfloat162float(h2));
    __nv_bfloat16 l3 = __float2bfloat16(v.w - __bfloat162float(h3));
    ushort4 ph = make_ushort4(__bfloat16_as_ushort(h0), __bfloat16_as_ushort(h1),
                              __bfloat16_as_ushort(h2), __bfloat16_as_ushort(h3));
    ushort4 pl = make_ushort4(__bfloat16_as_ushort(l0), __bfloat16_as_ushort(l1),
                              __bfloat16_as_ushort(l2), __bfloat16_as_ushort(l3));
    *(ushort4*)(xh + i) = ph;
    *(ushort4*)(xl + i) = pl;
}

// -------- tensor-core GEMM: C = relu( Ah*Bh + Ah*Bl + Al*Bh + bias ) ------
// Block tile 128x128, 8 warps (2 x 4), warp tile 64x32 (4x2 wmma frags).
// smem: double-buffered bf16 tiles [2][128][40] for A and B (ld=40 is
// conflict-free for ldmatrix at 80B row stride); epilogue reuses smem as
// float[128][132].
#define LDS_AB 40
#define LDS_C  132
#define TILE_ELEMS (128 * LDS_AB)

template <int WHICH>
__global__ __launch_bounds__(256) void gemm_wmma(float* __restrict__ Cout)
{
    constexpr int K = (WHICH == 0) ? C_OUT : C_IN;
    constexpr int KSTEPS = K / 32;
    constexpr int NSTEP = 3 * KSTEPS;

    const __nv_bfloat16* __restrict__ Ah = (WHICH == 0) ? g_x1h : g_x2h;
    const __nv_bfloat16* __restrict__ Al = (WHICH == 0) ? g_x1l : g_x2l;
    const __nv_bfloat16* __restrict__ Bh = (WHICH == 0) ? g_W1h : g_W2h;
    const __nv_bfloat16* __restrict__ Bl = (WHICH == 0) ? g_W1l : g_W2l;
    const float* __restrict__ cb = (WHICH == 0) ? g_c1 : g_c2;
    float* __restrict__ Cp = (WHICH == 0) ? Cout : g_h2;

    extern __shared__ __align__(16) char smem_raw[];
    __nv_bfloat16* As = (__nv_bfloat16*)smem_raw;          // [2][TILE_ELEMS]
    __nv_bfloat16* Bs = As + 2 * TILE_ELEMS;               // [2][TILE_ELEMS]
    float* Cs = (float*)smem_raw;                          // [128][132]

    const int tid = threadIdx.x;
    const int wid = tid >> 5;
    const int warp_m = wid >> 2;          // 0..1
    const int warp_n = wid & 3;           // 0..3
    const int bn = blockIdx.x * 128;
    const int bm = blockIdx.y * 128;

    wmma::fragment<wmma::accumulator, 16, 16, 16, float> acc[4][2];
#pragma unroll
    for (int i = 0; i < 4; i++)
#pragma unroll
        for (int j = 0; j < 2; j++) wmma::fill_fragment(acc[i][j], 0.0f);

    auto load_tile = [&](int s, int buf) {
        const int phase = s / KSTEPS;
        const int kk = (s % KSTEPS) * 32;
        const __nv_bfloat16* __restrict__ Ap = (phase == 2) ? Al : Ah;
        const __nv_bfloat16* __restrict__ Bp = (phase == 1) ? Bl : Bh;
#pragma unroll
        for (int j = 0; j < 2; j++) {
            int idx = tid + j * 256;            // 0..511
            int r = idx >> 2;
            int c8 = (idx & 3) * 8;
            uint4 va = *(const uint4*)(Ap + (size_t)(bm + r) * K + kk + c8);
            *(uint4*)(As + buf * TILE_ELEMS + r * LDS_AB + c8) = va;
            uint4 vb = *(const uint4*)(Bp + (size_t)(bn + r) * K + kk + c8);
            *(uint4*)(Bs + buf * TILE_ELEMS + r * LDS_AB + c8) = vb;
        }
    };

    load_tile(0, 0);
    __syncthreads();

    for (int s = 0; s < NSTEP; s++) {
        const int buf = s & 1;
        if (s + 1 < NSTEP) load_tile(s + 1, buf ^ 1);

        const __nv_bfloat16* Ab = As + buf * TILE_ELEMS;
        const __nv_bfloat16* Bb = Bs + buf * TILE_ELEMS;
#pragma unroll
        for (int kf = 0; kf < 2; kf++) {
            wmma::fragment<wmma::matrix_a, 16, 16, 16, __nv_bfloat16, wmma::row_major> af[4];
            wmma::fragment<wmma::matrix_b, 16, 16, 16, __nv_bfloat16, wmma::col_major> bf[2];
#pragma unroll
            for (int i = 0; i < 4; i++)
                wmma::load_matrix_sync(af[i], Ab + (warp_m * 64 + i * 16) * LDS_AB + kf * 16, LDS_AB);
#pragma unroll
            for (int j = 0; j < 2; j++)
                wmma::load_matrix_sync(bf[j], Bb + (warp_n * 32 + j * 16) * LDS_AB + kf * 16, LDS_AB);
#pragma unroll
            for (int i = 0; i < 4; i++)
#pragma unroll
                for (int j = 0; j < 2; j++)
                    wmma::mma_sync(acc[i][j], af[i], bf[j], acc[i][j]);
        }
        __syncthreads();
    }

    // epilogue: dump accum to smem (fp32), then bias + relu + vectorized store
#pragma unroll
    for (int i = 0; i < 4; i++)
#pragma unroll
        for (int j = 0; j < 2; j++)
            wmma::store_matrix_sync(Cs + (warp_m * 64 + i * 16) * LDS_C + warp_n * 32 + j * 16,
                                    acc[i][j], LDS_C, wmma::mem_row_major);
    __syncthreads();

    const int r = tid >> 1;
    const int cbase = (tid & 1) * 64;
    const float* csrow = Cs + r * LDS_C + cbase;
    float* orow = Cp + (size_t)(bm + r) * 256 + bn + cbase;
#pragma unroll
    for (int t = 0; t < 16; t++) {
        float4 v = *(const float4*)(csrow + t * 4);
        float4 bv = *(const float4*)(cb + bn + cbase + t * 4);
        v.x = fmaxf(v.x + bv.x, 0.f);
        v.y = fmaxf(v.y + bv.y, 0.f);
        v.z = fmaxf(v.z + bv.z, 0.f);
        v.w = fmaxf(v.w + bv.w, 0.f);
        *(float4*)(orow + t * 4) = v;
    }
}

// ---------------- kNN(k=3) + inverse-distance interp + add into out -------
// (R2 version: exact distances, proven rel_err 3.6e-7)
__global__ __launch_bounds__(256) void knn_interp_kernel(
    const float* __restrict__ p1, const float* __restrict__ p2,
    float* __restrict__ out)
{
    extern __shared__ float4 pts[];   // [4096]

    const int scene = blockIdx.y;
    const int tid   = threadIdx.x;

    const float* p2s = p2 + (size_t)scene * N2_PER * 3;
    for (int i = tid; i < N2_PER; i += 256) {
        pts[i] = make_float4(p2s[3 * i + 0], p2s[3 * i + 1], p2s[3 * i + 2], 0.f);
    }
    __syncthreads();

    const int q = scene * N1_PER + blockIdx.x * 256 + tid;
    const float qx = p1[3 * q + 0];
    const float qy = p1[3 * q + 1];
    const float qz = p1[3 * q + 2];

    float b0 = 3.4e38f, b1 = 3.4e38f, b2 = 3.4e38f;
    int   i0 = 0, i1 = 0, i2 = 0;

#pragma unroll 8
    for (int k = 0; k < N2_PER; k++) {
        float4 p = pts[k];
        float dx = qx - p.x, dy = qy - p.y, dz = qz - p.z;
        float d  = fmaf(dx, dx, fmaf(dy, dy, dz * dz));
        if (d < b2) {
            if (d < b1) {
                b2 = b1; i2 = i1;
                if (d < b0) { b1 = b0; i1 = i0; b0 = d; i0 = k; }
                else        { b1 = d;  i1 = k; }
            } else { b2 = d; i2 = k; }
        }
    }

    float w0 = 1.f / (sqrtf(fmaxf(b0, 1e-12f)) + 1e-8f);
    float w1 = 1.f / (sqrtf(fmaxf(b1, 1e-12f)) + 1e-8f);
    float w2 = 1.f / (sqrtf(fmaxf(b2, 1e-12f)) + 1e-8f);
    float ws = w0 + w1 + w2;
    w0 = w0 / ws; w1 = w1 / ws; w2 = w2 / ws;

    const unsigned full = 0xffffffffu;
    const int warp = tid >> 5, lane = tid & 31;
    const int h2base = scene * N2_PER;
    const int qbase  = scene * N1_PER + blockIdx.x * 256 + warp * 32;

    for (int s = 0; s < 32; s++) {
        float ww0 = __shfl_sync(full, w0, s);
        float ww1 = __shfl_sync(full, w1, s);
        float ww2 = __shfl_sync(full, w2, s);
        int   j0  = __shfl_sync(full, i0, s);
        int   j1  = __shfl_sync(full, i1, s);
        int   j2  = __shfl_sync(full, i2, s);
        const float4* r0 = (const float4*)(g_h2 + (size_t)(h2base + j0) * 256);
        const float4* r1 = (const float4*)(g_h2 + (size_t)(h2base + j1) * 256);
        const float4* r2 = (const float4*)(g_h2 + (size_t)(h2base + j2) * 256);
        float4* o = (float4*)(out + (size_t)(qbase + s) * 256);
#pragma unroll
        for (int c = 0; c < 2; c++) {
            int ci = lane + c * 32;
            float4 a = r0[ci], b = r1[ci], cc = r2[ci], ov = o[ci];
            ov.x += ww0 * a.x + ww1 * b.x + ww2 * cc.x;
            ov.y += ww0 * a.y + ww1 * b.y + ww2 * cc.y;
            ov.z += ww0 * a.z + ww1 * b.z + ww2 * cc.z;
            ov.w += ww0 * a.w + ww1 * b.w + ww2 * cc.w;
            o[ci] = ov;
        }
    }
}

// ---------------- launch -----------------
extern "C" void kernel_launch(void* const* d_in, const int* in_sizes, int n_in,
                              void* d_out, int out_size)
{
    const float* p1  = (const float*)d_in[0];
    const float* x1  = (const float*)d_in[1];
    const float* p2  = (const float*)d_in[2];
    const float* x2  = (const float*)d_in[3];
    const float* W1  = (const float*)d_in[4];
    const float* b1  = (const float*)d_in[5];
    const float* g1  = (const float*)d_in[6];
    const float* be1 = (const float*)d_in[7];
    const float* m1  = (const float*)d_in[8];
    const float* v1  = (const float*)d_in[9];
    const float* W2  = (const float*)d_in[10];
    const float* b2  = (const float*)d_in[11];
    const float* g2  = (const float*)d_in[12];
    const float* be2 = (const float*)d_in[13];
    const float* m2  = (const float*)d_in[14];
    const float* v2  = (const float*)d_in[15];
    float* out = (float*)d_out;

    // one-time attribute setup (idempotent, deterministic)
    static bool attr_set = false;
    if (!attr_set) {
        cudaFuncSetAttribute(gemm_wmma<0>, cudaFuncAttributeMaxDynamicSharedMemorySize,
                             128 * LDS_C * (int)sizeof(float));
        cudaFuncSetAttribute(gemm_wmma<1>, cudaFuncAttributeMaxDynamicSharedMemorySize,
                             128 * LDS_C * (int)sizeof(float));
        cudaFuncSetAttribute(knn_interp_kernel, cudaFuncAttributeMaxDynamicSharedMemorySize,
                             N2_PER * (int)sizeof(float4));
        attr_set = true;
    }

    // fold BN into weights + bf16 split
    fold_convert_W<0><<<C_OUT, 128>>>(W1, b1, g1, be1, m1, v1);
    fold_convert_W<1><<<C_OUT, 128>>>(W2, b2, g2, be2, m2, v2);

    // bf16 split of activations
    {
        __nv_bfloat16 *x1h, *x1l, *x2h, *x2l;
        cudaGetSymbolAddress((void**)&x1h, g_x1h);
        cudaGetSymbolAddress((void**)&x1l, g_x1l);
        cudaGetSymbolAddress((void**)&x2h, g_x2h);
        cudaGetSymbolAddress((void**)&x2l, g_x2l);
        int n1 = N1_TOT * C_OUT, n2 = N2_TOT * C_IN;
        convert_x<<<n1 / 4 / 256, 256>>>(x1, x1h, x1l, n1);
        convert_x<<<n2 / 4 / 256, 256>>>(x2, x2h, x2l, n2);
    }

    const int gemm_smem = 128 * LDS_C * (int)sizeof(float);

    // h1 = relu(bn(x1@W1^T)) -> out
    {
        dim3 grid1(2, N1_TOT / 128);
        gemm_wmma<0><<<grid1, 256, gemm_smem>>>(out);
    }
    // h2 = relu(bn(x2@W2^T)) -> g_h2
    {
        dim3 grid2(2, N2_TOT / 128);
        gemm_wmma<1><<<grid2, 256, gemm_smem>>>(out);
    }

    // kNN interpolation, accumulate into out
    dim3 gridk(N1_PER / 256, BATCH);
    knn_interp_kernel<<<gridk, 256, N2_PER * sizeof(float4)>>>(p1, p2, out);
}